// round 1
// baseline (speedup 1.0000x reference)
#include <cuda_runtime.h>

// Shapes (fixed): B=8, H=12, D=64, S=1024
// scores[b,h,s,t] = (1/8) * sum_d K[b,h,d,s] * Q[b,h,d,t]
// mask over t, softmax over t (per s-row), context[b,h,d,t] = sum_s V[b,h,d,s]*attn[b,h,s,t]
// out = concat( context as (B,S,H*D), attn as (B,H,S,S) )

#define D_DIM 64
#define S_DIM 1024
#define H_NUM 12
#define B_NUM 8
#define NBH   (B_NUM * H_NUM)

// ---------------------------------------------------------------------------
// Kernel 1: QK^T GEMM. C tile 64(s) x 64(t), K-dim = 64 (d). Writes raw
// scaled scores into the attn region of the output buffer (scratch reuse).
// ---------------------------------------------------------------------------
__global__ __launch_bounds__(256) void qk_kernel(
    const float* __restrict__ Q, const float* __restrict__ K,
    float* __restrict__ attn)
{
    const int bh = blockIdx.z;
    const int s0 = blockIdx.y * 64;
    const int t0 = blockIdx.x * 64;
    const float* Kb = K + (size_t)bh * D_DIM * S_DIM;
    const float* Qb = Q + (size_t)bh * D_DIM * S_DIM;

    __shared__ float As[16][64];  // [d_chunk][s]
    __shared__ float Bs[16][64];  // [d_chunk][t]

    const int tid = threadIdx.x;
    const int tx = tid & 15;      // -> t micro
    const int ty = tid >> 4;      // -> s micro
    const int lr = tid >> 4;      // load row (d)
    const int lc = (tid & 15) * 4;// load col

    float c[4][4];
#pragma unroll
    for (int i = 0; i < 4; i++)
#pragma unroll
        for (int j = 0; j < 4; j++) c[i][j] = 0.f;

#pragma unroll
    for (int k0 = 0; k0 < 64; k0 += 16) {
        *(float4*)&As[lr][lc] = *(const float4*)&Kb[(size_t)(k0 + lr) * S_DIM + s0 + lc];
        *(float4*)&Bs[lr][lc] = *(const float4*)&Qb[(size_t)(k0 + lr) * S_DIM + t0 + lc];
        __syncthreads();
#pragma unroll
        for (int k = 0; k < 16; k++) {
            float a[4], b[4];
            *(float4*)a = *(float4*)&As[k][ty * 4];
            *(float4*)b = *(float4*)&Bs[k][tx * 4];
#pragma unroll
            for (int i = 0; i < 4; i++)
#pragma unroll
                for (int j = 0; j < 4; j++) c[i][j] += a[i] * b[j];
        }
        __syncthreads();
    }

    // write raw scaled scores (mask applied later in softmax)
    float* arow = attn + ((size_t)bh * S_DIM + (s0 + ty * 4)) * S_DIM + t0 + tx * 4;
#pragma unroll
    for (int i = 0; i < 4; i++) {
        float4 v = make_float4(c[i][0] * 0.125f, c[i][1] * 0.125f,
                               c[i][2] * 0.125f, c[i][3] * 0.125f);
        *(float4*)(arow + (size_t)i * S_DIM) = v;
    }
}

// ---------------------------------------------------------------------------
// Kernel 2: per-row mask + softmax over t, in place. One 256-thread block per
// (bh, s) row; each thread owns 4 contiguous t.
// ---------------------------------------------------------------------------
__global__ __launch_bounds__(256) void softmax_kernel(
    float* __restrict__ attn, const int* __restrict__ mask)
{
    const int s = blockIdx.x;
    const int bh = blockIdx.y;
    const int b = bh / H_NUM;
    float* rowp = attn + ((size_t)bh * S_DIM + s) * S_DIM;
    const int* mrow = mask + (size_t)b * S_DIM;
    const int tid = threadIdx.x;

    float4 v = *(float4*)(rowp + tid * 4);
    const int4 mv = *(const int4*)(mrow + tid * 4);
    if (mv.x == 0) v.x = -1e9f;
    if (mv.y == 0) v.y = -1e9f;
    if (mv.z == 0) v.z = -1e9f;
    if (mv.w == 0) v.w = -1e9f;

    __shared__ float redm[8];
    __shared__ float reds[8];

    // max reduce
    float m = fmaxf(fmaxf(v.x, v.y), fmaxf(v.z, v.w));
#pragma unroll
    for (int o = 16; o > 0; o >>= 1)
        m = fmaxf(m, __shfl_xor_sync(0xffffffffu, m, o));
    if ((tid & 31) == 0) redm[tid >> 5] = m;
    __syncthreads();
    if (tid == 0) {
        float mm = redm[0];
#pragma unroll
        for (int i = 1; i < 8; i++) mm = fmaxf(mm, redm[i]);
        redm[0] = mm;
    }
    __syncthreads();
    m = redm[0];

    const float e0 = __expf(v.x - m);
    const float e1 = __expf(v.y - m);
    const float e2 = __expf(v.z - m);
    const float e3 = __expf(v.w - m);

    float sum = (e0 + e1) + (e2 + e3);
#pragma unroll
    for (int o = 16; o > 0; o >>= 1)
        sum += __shfl_xor_sync(0xffffffffu, sum, o);
    if ((tid & 31) == 0) reds[tid >> 5] = sum;
    __syncthreads();
    if (tid == 0) {
        float t = 0.f;
#pragma unroll
        for (int i = 0; i < 8; i++) t += reds[i];
        reds[0] = t;
    }
    __syncthreads();
    const float inv = 1.0f / reds[0];

    *(float4*)(rowp + tid * 4) = make_float4(e0 * inv, e1 * inv, e2 * inv, e3 * inv);
}

// ---------------------------------------------------------------------------
// Kernel 3: PV GEMM. C tile 64(d) x 64(t) per bh, K-dim = 1024 (s).
// Writes context in (B, S, H*D) layout: out[(b*S + t)*768 + h*64 + d].
// ---------------------------------------------------------------------------
__global__ __launch_bounds__(256) void pv_kernel(
    const float* __restrict__ V, const float* __restrict__ attn,
    float* __restrict__ outctx)
{
    const int bh = blockIdx.z;
    const int t0 = blockIdx.x * 64;
    const int b = bh / H_NUM;
    const int h = bh - b * H_NUM;
    const float* Vb = V + (size_t)bh * D_DIM * S_DIM;
    const float* Ab = attn + (size_t)bh * S_DIM * S_DIM;

    __shared__ float Vs[16][68];   // [s_local][d], padded
    __shared__ float As2[16][64];  // [s_local][t]

    const int tid = threadIdx.x;
    const int tx = tid & 15;   // -> t micro
    const int ty = tid >> 4;   // -> d micro
    const int lr = tid >> 4;   // attn load row (s)
    const int lc = (tid & 15) * 4;
    const int vd = tid >> 2;        // V load: d = 0..63
    const int vs = (tid & 3) * 4;   // V load: s offset 0..12

    float c[4][4];
#pragma unroll
    for (int i = 0; i < 4; i++)
#pragma unroll
        for (int j = 0; j < 4; j++) c[i][j] = 0.f;

    for (int s0 = 0; s0 < S_DIM; s0 += 16) {
        // V tile transposed into smem: Vs[s][d]
        float4 vv = *(const float4*)&Vb[(size_t)vd * S_DIM + s0 + vs];
        Vs[vs + 0][vd] = vv.x;
        Vs[vs + 1][vd] = vv.y;
        Vs[vs + 2][vd] = vv.z;
        Vs[vs + 3][vd] = vv.w;
        // attn tile: As2[s][t]
        *(float4*)&As2[lr][lc] = *(const float4*)&Ab[(size_t)(s0 + lr) * S_DIM + t0 + lc];
        __syncthreads();
#pragma unroll
        for (int k = 0; k < 16; k++) {
            float a[4], bb[4];
            *(float4*)a = *(float4*)&Vs[k][ty * 4];
            *(float4*)bb = *(float4*)&As2[k][tx * 4];
#pragma unroll
            for (int i = 0; i < 4; i++)
#pragma unroll
                for (int j = 0; j < 4; j++) c[i][j] += a[i] * bb[j];
        }
        __syncthreads();
    }

    // context out: out[(b*S + t)*768 + h*64 + d], float4 along d
#pragma unroll
    for (int j = 0; j < 4; j++) {
        const int t = t0 + tx * 4 + j;
        float4 v = make_float4(c[0][j], c[1][j], c[2][j], c[3][j]);
        *(float4*)&outctx[((size_t)b * S_DIM + t) * (H_NUM * D_DIM) + h * D_DIM + ty * 4] = v;
    }
}

// ---------------------------------------------------------------------------
extern "C" void kernel_launch(void* const* d_in, const int* in_sizes, int n_in,
                              void* d_out, int out_size)
{
    (void)in_sizes; (void)n_in; (void)out_size;
    const float* Q = (const float*)d_in[0];
    const float* K = (const float*)d_in[1];
    const float* V = (const float*)d_in[2];
    const int* mask = (const int*)d_in[3];

    float* ctx = (float*)d_out;                                   // (B, S, H*D)
    float* attn = ctx + (size_t)B_NUM * S_DIM * H_NUM * D_DIM;    // (B, H, S, S)

    qk_kernel<<<dim3(16, 16, NBH), 256>>>(Q, K, attn);
    softmax_kernel<<<dim3(S_DIM, NBH), 256>>>(attn, mask);
    pv_kernel<<<dim3(16, 1, NBH), 256>>>(V, attn, ctx);
}

// round 2
// speedup vs baseline: 1.0618x; 1.0618x over previous
#include <cuda_runtime.h>

// Shapes (fixed): B=8, H=12, D=64, S=1024
// scores[b,h,s,t] = (1/8) * sum_d K[b,h,d,s] * Q[b,h,d,t]
// mask over t (per b), softmax over t (per (bh,s) row),
// context[b,h,d,t] = sum_s V[b,h,d,s]*attn[b,h,s,t]
// out = concat( context as (B,S,H*D), attn as (B,H,S,S) )
//
// Pipeline:
//   qk_kernel: 128x128 GEMM tiles with packed fma.rn.f32x2; epilogue applies
//              mask, computes unnormalized e=exp(score/8), writes E into the
//              attn output region, and writes deterministic per-(row,t-block)
//              partial sums to g_part (no atomics).
//   pv_kernel: builds inv rowsums from g_part, reads E once, normalizes it
//              (writes normalized attn back in place) and computes context.

#define D_DIM 64
#define S_DIM 1024
#define H_NUM 12
#define B_NUM 8
#define NBH   (B_NUM * H_NUM)

typedef unsigned long long ull;

__device__ __forceinline__ ull pack_dup(float x) {
    ull r; asm("mov.b64 %0, {%1,%2};" : "=l"(r) : "f"(x), "f"(x)); return r;
}
__device__ __forceinline__ void unpack2(ull v, float& lo, float& hi) {
    asm("mov.b64 {%0,%1}, %2;" : "=f"(lo), "=f"(hi) : "l"(v));
}
__device__ __forceinline__ ull fma2(ull a, ull b, ull c) {
    ull d; asm("fma.rn.f32x2 %0, %1, %2, %3;" : "=l"(d) : "l"(a), "l"(b), "l"(c));
    return d;
}

// Partial row sums: [t_block(8)][bh(96)][s(1024)]
__device__ float g_part[8 * NBH * S_DIM];

// ---------------------------------------------------------------------------
// Kernel 1: QK^T GEMM + exp + mask. Tile 128(s) x 128(t), K = 64 (d).
// Thread micro-tile: 16(s, packed in f32x2 pairs) x 4(t).
// ---------------------------------------------------------------------------
__global__ __launch_bounds__(256, 2) void qk_kernel(
    const float* __restrict__ Q, const float* __restrict__ K,
    const int* __restrict__ mask, float* __restrict__ attn)
{
    const int bh = blockIdx.z;
    const int s0 = blockIdx.y * 128;
    const int t0 = blockIdx.x * 128;
    const float* Kb = K + (size_t)bh * D_DIM * S_DIM;
    const float* Qb = Q + (size_t)bh * D_DIM * S_DIM;

    __shared__ float As[32][128];   // [d_chunk][s]
    __shared__ float Bs[32][128];   // [d_chunk][t]

    const int tid = threadIdx.x;
    const int tx = tid & 31;        // t micro: t0 + tx*4 + j
    const int ty = tid >> 5;        // s micro: s0 + ty*16 + r

    ull c[8][4];
#pragma unroll
    for (int i = 0; i < 8; i++)
#pragma unroll
        for (int j = 0; j < 4; j++) c[i][j] = 0ULL;

#pragma unroll
    for (int ch = 0; ch < 2; ch++) {
#pragma unroll
        for (int j = 0; j < 4; j++) {
            const int lin = tid + j * 256;
            const int row = lin >> 5;
            const int col = (lin & 31) * 4;
            *(float4*)&As[row][col] =
                *(const float4*)&Kb[(size_t)(ch * 32 + row) * S_DIM + s0 + col];
            *(float4*)&Bs[row][col] =
                *(const float4*)&Qb[(size_t)(ch * 32 + row) * S_DIM + t0 + col];
        }
        __syncthreads();
#pragma unroll
        for (int k = 0; k < 32; k++) {
            const ulonglong2 a01 = *(const ulonglong2*)&As[k][ty * 16];
            const ulonglong2 a23 = *(const ulonglong2*)&As[k][ty * 16 + 4];
            const ulonglong2 a45 = *(const ulonglong2*)&As[k][ty * 16 + 8];
            const ulonglong2 a67 = *(const ulonglong2*)&As[k][ty * 16 + 12];
            const float4 bv = *(const float4*)&Bs[k][tx * 4];
            const ull bd0 = pack_dup(bv.x);
            const ull bd1 = pack_dup(bv.y);
            const ull bd2 = pack_dup(bv.z);
            const ull bd3 = pack_dup(bv.w);
            ull a[8] = {a01.x, a01.y, a23.x, a23.y, a45.x, a45.y, a67.x, a67.y};
#pragma unroll
            for (int i = 0; i < 8; i++) {
                c[i][0] = fma2(a[i], bd0, c[i][0]);
                c[i][1] = fma2(a[i], bd1, c[i][1]);
                c[i][2] = fma2(a[i], bd2, c[i][2]);
                c[i][3] = fma2(a[i], bd3, c[i][3]);
            }
        }
        __syncthreads();
    }

    // Epilogue: scale, mask, exp, store E, partial row sums.
    const int b = bh / H_NUM;
    const int4 mv = *(const int4*)&mask[b * S_DIM + t0 + tx * 4];
    const float m0 = mv.x ? 1.f : 0.f;
    const float m1 = mv.y ? 1.f : 0.f;
    const float m2 = mv.z ? 1.f : 0.f;
    const float m3 = mv.w ? 1.f : 0.f;

    float rs[16];
    const size_t base = ((size_t)bh * S_DIM + (s0 + ty * 16)) * S_DIM + t0 + tx * 4;
#pragma unroll
    for (int i = 0; i < 8; i++) {
        float l0, h0, l1, h1, l2, h2, l3, h3;
        unpack2(c[i][0], l0, h0);
        unpack2(c[i][1], l1, h1);
        unpack2(c[i][2], l2, h2);
        unpack2(c[i][3], l3, h3);
        float4 e0 = make_float4(__expf(l0 * 0.125f) * m0, __expf(l1 * 0.125f) * m1,
                                __expf(l2 * 0.125f) * m2, __expf(l3 * 0.125f) * m3);
        float4 e1 = make_float4(__expf(h0 * 0.125f) * m0, __expf(h1 * 0.125f) * m1,
                                __expf(h2 * 0.125f) * m2, __expf(h3 * 0.125f) * m3);
        *(float4*)&attn[base + (size_t)(2 * i) * S_DIM] = e0;
        *(float4*)&attn[base + (size_t)(2 * i + 1) * S_DIM] = e1;
        rs[2 * i]     = (e0.x + e0.y) + (e0.z + e0.w);
        rs[2 * i + 1] = (e1.x + e1.y) + (e1.z + e1.w);
    }
#pragma unroll
    for (int r = 0; r < 16; r++) {
        float v = rs[r];
#pragma unroll
        for (int o = 16; o > 0; o >>= 1)
            v += __shfl_xor_sync(0xffffffffu, v, o);
        rs[r] = v;
    }
    if (tx == 0) {
        float* pp = &g_part[((blockIdx.x * NBH + bh) << 10) + s0 + ty * 16];
#pragma unroll
        for (int r4 = 0; r4 < 4; r4++)
            *(float4*)&pp[r4 * 4] =
                make_float4(rs[r4 * 4], rs[r4 * 4 + 1], rs[r4 * 4 + 2], rs[r4 * 4 + 3]);
    }
}

// ---------------------------------------------------------------------------
// Kernel 2: PV GEMM + normalize. Tile 64(d) x 64(t) per block, K = 1024 (s).
// Thread micro-tile: 8(d, packed pairs) x 2(t). Normalized attn written back.
// ---------------------------------------------------------------------------
__global__ __launch_bounds__(256, 2) void pv_kernel(
    const float* __restrict__ V, float* __restrict__ attn,
    float* __restrict__ ctx)
{
    const int bh = blockIdx.y;
    const int t0 = blockIdx.x * 64;
    const int b = bh / H_NUM;
    const int h = bh - b * H_NUM;
    const float* Vb = V + (size_t)bh * D_DIM * S_DIM;
    float* Ab = attn + (size_t)bh * S_DIM * S_DIM;

    __shared__ float Vs[32][68];      // [s_local][d], padded
    __shared__ float Es[32][64];      // [s_local][t]
    __shared__ float inv_s[S_DIM];

    const int tid = threadIdx.x;
    const int tx = tid & 31;          // t micro: t0 + tx*2 + j
    const int ty = tid >> 5;          // d micro: ty*8 + 2i + {0,1}

    // Build 1/rowsum for all s of this bh (deterministic 8-way sum).
#pragma unroll
    for (int j = 0; j < 4; j++) {
        const int s = tid + j * 256;
        float sum = 0.f;
#pragma unroll
        for (int tb = 0; tb < 8; tb++)
            sum += g_part[((tb * NBH + bh) << 10) + s];
        inv_s[s] = 1.0f / sum;
    }
    __syncthreads();

    ull c[4][2];
#pragma unroll
    for (int i = 0; i < 4; i++)
#pragma unroll
        for (int j = 0; j < 2; j++) c[i][j] = 0ULL;

    const int vd = tid >> 2;          // 0..63
    const int vs = (tid & 3) * 8;     // 0,8,16,24

    for (int sc = 0; sc < S_DIM; sc += 32) {
        // V tile transposed into smem: Vs[s][d]
        const float4 v0 = *(const float4*)&Vb[(size_t)vd * S_DIM + sc + vs];
        const float4 v1 = *(const float4*)&Vb[(size_t)vd * S_DIM + sc + vs + 4];
        Vs[vs + 0][vd] = v0.x; Vs[vs + 1][vd] = v0.y;
        Vs[vs + 2][vd] = v0.z; Vs[vs + 3][vd] = v0.w;
        Vs[vs + 4][vd] = v1.x; Vs[vs + 5][vd] = v1.y;
        Vs[vs + 6][vd] = v1.z; Vs[vs + 7][vd] = v1.w;
        // E tile: load, normalize, write normalized attn back, stage in smem
#pragma unroll
        for (int j = 0; j < 2; j++) {
            const int lin = tid + j * 256;
            const int row = lin >> 4;
            const int col = (lin & 15) * 4;
            const size_t gi = (size_t)(sc + row) * S_DIM + t0 + col;
            float4 ev = *(const float4*)&Ab[gi];
            const float iv = inv_s[sc + row];
            ev.x *= iv; ev.y *= iv; ev.z *= iv; ev.w *= iv;
            *(float4*)&Es[row][col] = ev;
            *(float4*)&Ab[gi] = ev;
        }
        __syncthreads();
#pragma unroll
        for (int k = 0; k < 32; k++) {
            const ulonglong2 a01 = *(const ulonglong2*)&Vs[k][ty * 8];
            const ulonglong2 a23 = *(const ulonglong2*)&Vs[k][ty * 8 + 4];
            const float2 bv = *(const float2*)&Es[k][tx * 2];
            const ull bd0 = pack_dup(bv.x);
            const ull bd1 = pack_dup(bv.y);
            c[0][0] = fma2(a01.x, bd0, c[0][0]);
            c[0][1] = fma2(a01.x, bd1, c[0][1]);
            c[1][0] = fma2(a01.y, bd0, c[1][0]);
            c[1][1] = fma2(a01.y, bd1, c[1][1]);
            c[2][0] = fma2(a23.x, bd0, c[2][0]);
            c[2][1] = fma2(a23.x, bd1, c[2][1]);
            c[3][0] = fma2(a23.y, bd0, c[3][0]);
            c[3][1] = fma2(a23.y, bd1, c[3][1]);
        }
        __syncthreads();
    }

    // context out: ctx[(b*S + t)*768 + h*64 + d]
#pragma unroll
    for (int j = 0; j < 2; j++) {
        const int t = t0 + tx * 2 + j;
        float f0, f1, f2, f3, f4, f5, f6, f7;
        unpack2(c[0][j], f0, f1);
        unpack2(c[1][j], f2, f3);
        unpack2(c[2][j], f4, f5);
        unpack2(c[3][j], f6, f7);
        float* op = &ctx[((size_t)b * S_DIM + t) * (H_NUM * D_DIM) + h * D_DIM + ty * 8];
        *(float4*)op       = make_float4(f0, f1, f2, f3);
        *(float4*)(op + 4) = make_float4(f4, f5, f6, f7);
    }
}

// ---------------------------------------------------------------------------
extern "C" void kernel_launch(void* const* d_in, const int* in_sizes, int n_in,
                              void* d_out, int out_size)
{
    (void)in_sizes; (void)n_in; (void)out_size;
    const float* Q = (const float*)d_in[0];
    const float* K = (const float*)d_in[1];
    const float* V = (const float*)d_in[2];
    const int* mask = (const int*)d_in[3];

    float* ctx  = (float*)d_out;                                   // (B, S, H*D)
    float* attn = ctx + (size_t)B_NUM * S_DIM * H_NUM * D_DIM;     // (B, H, S, S)

    qk_kernel<<<dim3(8, 8, NBH), 256>>>(Q, K, mask, attn);
    pv_kernel<<<dim3(16, NBH), 256>>>(V, attn, ctx);
}

// round 3
// speedup vs baseline: 1.3446x; 1.2664x over previous
#include <cuda_runtime.h>

// Shapes (fixed): B=8, H=12, D=64, S=1024
// scores[b,h,s,t] = (1/8) * sum_d K[b,h,d,s] * Q[b,h,d,t]
// mask over t (per b), softmax over t (per (bh,s) row),
// context[b,h,d,t] = sum_s V[b,h,d,s]*attn[b,h,s,t]
// out = concat( context as (B,S,H*D), attn as (B,H,S,S) )

#define D_DIM 64
#define S_DIM 1024
#define H_NUM 12
#define B_NUM 8
#define NBH   (B_NUM * H_NUM)
#define CTX_ELEMS ((size_t)B_NUM * S_DIM * H_NUM * D_DIM)   // 6291456

typedef unsigned long long ull;

__device__ __forceinline__ ull pack_dup(float x) {
    ull r; asm("mov.b64 %0, {%1,%2};" : "=l"(r) : "f"(x), "f"(x)); return r;
}
__device__ __forceinline__ void unpack2(ull v, float& lo, float& hi) {
    asm("mov.b64 {%0,%1}, %2;" : "=f"(lo), "=f"(hi) : "l"(v));
}
__device__ __forceinline__ ull fma2(ull a, ull b, ull c) {
    ull d; asm("fma.rn.f32x2 %0, %1, %2, %3;" : "=l"(d) : "l"(a), "l"(b), "l"(c));
    return d;
}

// Partial row sums from qk: [t_block(8)][bh(96)][s(1024)]
__device__ float g_part[8 * NBH * S_DIM];
// Partial context from pv s-splits: [s_chunk(4)][ctx layout]
__device__ float g_ctxp[4 * CTX_ELEMS];

// ---------------------------------------------------------------------------
// Kernel 1: QK^T GEMM + exp + mask. Tile 128(s) x 128(t), K = 64 (d).
// Thread micro-tile: 16(s, packed f32x2) x 4(t). Writes unnormalized E and
// deterministic per-(row, t-block) partial sums.
// ---------------------------------------------------------------------------
__global__ __launch_bounds__(256, 2) void qk_kernel(
    const float* __restrict__ Q, const float* __restrict__ K,
    const int* __restrict__ mask, float* __restrict__ attn)
{
    const int bh = blockIdx.z;
    const int s0 = blockIdx.y * 128;
    const int t0 = blockIdx.x * 128;
    const float* Kb = K + (size_t)bh * D_DIM * S_DIM;
    const float* Qb = Q + (size_t)bh * D_DIM * S_DIM;

    __shared__ float As[32][128];   // [d_chunk][s]
    __shared__ float Bs[32][128];   // [d_chunk][t]

    const int tid = threadIdx.x;
    const int tx = tid & 31;        // t micro: t0 + tx*4 + j
    const int ty = tid >> 5;        // s micro: s0 + ty*16 + r

    ull c[8][4];
#pragma unroll
    for (int i = 0; i < 8; i++)
#pragma unroll
        for (int j = 0; j < 4; j++) c[i][j] = 0ULL;

#pragma unroll
    for (int ch = 0; ch < 2; ch++) {
#pragma unroll
        for (int j = 0; j < 4; j++) {
            const int lin = tid + j * 256;
            const int row = lin >> 5;
            const int col = (lin & 31) * 4;
            *(float4*)&As[row][col] =
                *(const float4*)&Kb[(size_t)(ch * 32 + row) * S_DIM + s0 + col];
            *(float4*)&Bs[row][col] =
                *(const float4*)&Qb[(size_t)(ch * 32 + row) * S_DIM + t0 + col];
        }
        __syncthreads();
#pragma unroll
        for (int k = 0; k < 32; k++) {
            const ulonglong2 a01 = *(const ulonglong2*)&As[k][ty * 16];
            const ulonglong2 a23 = *(const ulonglong2*)&As[k][ty * 16 + 4];
            const ulonglong2 a45 = *(const ulonglong2*)&As[k][ty * 16 + 8];
            const ulonglong2 a67 = *(const ulonglong2*)&As[k][ty * 16 + 12];
            const float4 bv = *(const float4*)&Bs[k][tx * 4];
            const ull bd0 = pack_dup(bv.x);
            const ull bd1 = pack_dup(bv.y);
            const ull bd2 = pack_dup(bv.z);
            const ull bd3 = pack_dup(bv.w);
            ull a[8] = {a01.x, a01.y, a23.x, a23.y, a45.x, a45.y, a67.x, a67.y};
#pragma unroll
            for (int i = 0; i < 8; i++) {
                c[i][0] = fma2(a[i], bd0, c[i][0]);
                c[i][1] = fma2(a[i], bd1, c[i][1]);
                c[i][2] = fma2(a[i], bd2, c[i][2]);
                c[i][3] = fma2(a[i], bd3, c[i][3]);
            }
        }
        __syncthreads();
    }

    // Epilogue: scale, mask, exp, store E, partial row sums.
    const int b = bh / H_NUM;
    const int4 mv = *(const int4*)&mask[b * S_DIM + t0 + tx * 4];
    const float m0 = mv.x ? 1.f : 0.f;
    const float m1 = mv.y ? 1.f : 0.f;
    const float m2 = mv.z ? 1.f : 0.f;
    const float m3 = mv.w ? 1.f : 0.f;

    float rs[16];
    const size_t base = ((size_t)bh * S_DIM + (s0 + ty * 16)) * S_DIM + t0 + tx * 4;
#pragma unroll
    for (int i = 0; i < 8; i++) {
        float l0, h0, l1, h1, l2, h2, l3, h3;
        unpack2(c[i][0], l0, h0);
        unpack2(c[i][1], l1, h1);
        unpack2(c[i][2], l2, h2);
        unpack2(c[i][3], l3, h3);
        float4 e0 = make_float4(__expf(l0 * 0.125f) * m0, __expf(l1 * 0.125f) * m1,
                                __expf(l2 * 0.125f) * m2, __expf(l3 * 0.125f) * m3);
        float4 e1 = make_float4(__expf(h0 * 0.125f) * m0, __expf(h1 * 0.125f) * m1,
                                __expf(h2 * 0.125f) * m2, __expf(h3 * 0.125f) * m3);
        *(float4*)&attn[base + (size_t)(2 * i) * S_DIM] = e0;
        *(float4*)&attn[base + (size_t)(2 * i + 1) * S_DIM] = e1;
        rs[2 * i]     = (e0.x + e0.y) + (e0.z + e0.w);
        rs[2 * i + 1] = (e1.x + e1.y) + (e1.z + e1.w);
    }
#pragma unroll
    for (int r = 0; r < 16; r++) {
        float v = rs[r];
#pragma unroll
        for (int o = 16; o > 0; o >>= 1)
            v += __shfl_xor_sync(0xffffffffu, v, o);
        rs[r] = v;
    }
    if (tx == 0) {
        float* pp = &g_part[((blockIdx.x * NBH + bh) << 10) + s0 + ty * 16];
#pragma unroll
        for (int r4 = 0; r4 < 4; r4++)
            *(float4*)&pp[r4 * 4] =
                make_float4(rs[r4 * 4], rs[r4 * 4 + 1], rs[r4 * 4 + 2], rs[r4 * 4 + 3]);
    }
}

// ---------------------------------------------------------------------------
// Kernel 2: PV GEMM + normalize (double-buffered). Tile 64(d) x 128(t) per
// block over a 256-s chunk. Thread micro-tile: 8(d, packed) x 4(t).
// Normalized attn written back; partial context to g_ctxp[s_chunk].
// ---------------------------------------------------------------------------
__global__ __launch_bounds__(256, 2) void pv_kernel(
    const float* __restrict__ V, float* __restrict__ attn)
{
    const int bh = blockIdx.z;
    const int t0 = blockIdx.x * 128;
    const int sc0 = blockIdx.y * 256;
    const int b = bh / H_NUM;
    const int h = bh - b * H_NUM;
    const float* Vb = V + (size_t)bh * D_DIM * S_DIM;
    float* Ab = attn + (size_t)bh * S_DIM * S_DIM;

    __shared__ float Es[2][32][128];   // ping-pong E tiles [s_local][t]
    __shared__ float Vs[32][68];       // single-buffered V tile [s_local][d]
    __shared__ float inv_s[256];

    const int tid = threadIdx.x;

    // 1/rowsum for this CTA's 256 s rows (deterministic 8-way sum).
    {
        float sum = 0.f;
#pragma unroll
        for (int tb = 0; tb < 8; tb++)
            sum += g_part[((tb * NBH + bh) << 10) + sc0 + tid];
        inv_s[tid] = 1.0f / sum;
    }
    __syncthreads();

    const int erow = tid >> 3;            // E row within chunk (0..31)
    const int ecol = (tid & 7) * 4;       // E col base; q-stride 32 (bank-clean)
    const int vd = tid >> 2;              // V: d index (0..63)
    const int vso = (tid & 3) * 8;        // V: s offset within chunk
    const int tx = tid & 31;              // t micro: t0 + tx*4 + j
    const int ty = tid >> 5;              // d micro: ty*8 + ...

    // ---- prologue: chunk 0 directly into buffer 0 ----
    {
        const float iv = inv_s[erow];
#pragma unroll
        for (int q = 0; q < 4; q++) {
            const size_t gi = (size_t)(sc0 + erow) * S_DIM + t0 + ecol + q * 32;
            float4 ev = *(const float4*)&Ab[gi];
            ev.x *= iv; ev.y *= iv; ev.z *= iv; ev.w *= iv;
            *(float4*)&Ab[gi] = ev;
            *(float4*)&Es[0][erow][ecol + q * 32] = ev;
        }
        const float4 v0 = *(const float4*)&Vb[(size_t)vd * S_DIM + sc0 + vso];
        const float4 v1 = *(const float4*)&Vb[(size_t)vd * S_DIM + sc0 + vso + 4];
        Vs[vso + 0][vd] = v0.x; Vs[vso + 1][vd] = v0.y;
        Vs[vso + 2][vd] = v0.z; Vs[vso + 3][vd] = v0.w;
        Vs[vso + 4][vd] = v1.x; Vs[vso + 5][vd] = v1.y;
        Vs[vso + 6][vd] = v1.z; Vs[vso + 7][vd] = v1.w;
    }
    __syncthreads();

    ull c[4][4];   // [t j][d pair i]
#pragma unroll
    for (int j = 0; j < 4; j++)
#pragma unroll
        for (int i = 0; i < 4; i++) c[j][i] = 0ULL;

    float4 ePre[4], vPre[2];

    for (int ci = 0; ci < 8; ci++) {
        const int cur = ci & 1;
        const int nxt = cur ^ 1;
        // prefetch next chunk to regs (+ normalized attn write-back)
        if (ci < 7) {
            const int sb = sc0 + (ci + 1) * 32;
            const float iv = inv_s[(ci + 1) * 32 + erow];
#pragma unroll
            for (int q = 0; q < 4; q++) {
                const size_t gi = (size_t)(sb + erow) * S_DIM + t0 + ecol + q * 32;
                float4 ev = *(const float4*)&Ab[gi];
                ev.x *= iv; ev.y *= iv; ev.z *= iv; ev.w *= iv;
                *(float4*)&Ab[gi] = ev;
                ePre[q] = ev;
            }
            vPre[0] = *(const float4*)&Vb[(size_t)vd * S_DIM + sb + vso];
            vPre[1] = *(const float4*)&Vb[(size_t)vd * S_DIM + sb + vso + 4];
        }
        // compute current chunk
#pragma unroll
        for (int k = 0; k < 32; k++) {
            const ulonglong2 a01 = *(const ulonglong2*)&Vs[k][ty * 8];
            const ulonglong2 a23 = *(const ulonglong2*)&Vs[k][ty * 8 + 4];
            const float4 bv = *(const float4*)&Es[cur][k][tx * 4];
            const ull bd0 = pack_dup(bv.x);
            const ull bd1 = pack_dup(bv.y);
            const ull bd2 = pack_dup(bv.z);
            const ull bd3 = pack_dup(bv.w);
            c[0][0] = fma2(a01.x, bd0, c[0][0]);
            c[0][1] = fma2(a01.y, bd0, c[0][1]);
            c[0][2] = fma2(a23.x, bd0, c[0][2]);
            c[0][3] = fma2(a23.y, bd0, c[0][3]);
            c[1][0] = fma2(a01.x, bd1, c[1][0]);
            c[1][1] = fma2(a01.y, bd1, c[1][1]);
            c[1][2] = fma2(a23.x, bd1, c[1][2]);
            c[1][3] = fma2(a23.y, bd1, c[1][3]);
            c[2][0] = fma2(a01.x, bd2, c[2][0]);
            c[2][1] = fma2(a01.y, bd2, c[2][1]);
            c[2][2] = fma2(a23.x, bd2, c[2][2]);
            c[2][3] = fma2(a23.y, bd2, c[2][3]);
            c[3][0] = fma2(a01.x, bd3, c[3][0]);
            c[3][1] = fma2(a01.y, bd3, c[3][1]);
            c[3][2] = fma2(a23.x, bd3, c[3][2]);
            c[3][3] = fma2(a23.y, bd3, c[3][3]);
        }
        __syncthreads();
        if (ci < 7) {
#pragma unroll
            for (int q = 0; q < 4; q++)
                *(float4*)&Es[nxt][erow][ecol + q * 32] = ePre[q];
            Vs[vso + 0][vd] = vPre[0].x; Vs[vso + 1][vd] = vPre[0].y;
            Vs[vso + 2][vd] = vPre[0].z; Vs[vso + 3][vd] = vPre[0].w;
            Vs[vso + 4][vd] = vPre[1].x; Vs[vso + 5][vd] = vPre[1].y;
            Vs[vso + 6][vd] = vPre[1].z; Vs[vso + 7][vd] = vPre[1].w;
            __syncthreads();
        }
    }

    // partial context: g_ctxp[sc][(b*S + t)*768 + h*64 + d]
    float* P = g_ctxp + (size_t)blockIdx.y * CTX_ELEMS;
#pragma unroll
    for (int j = 0; j < 4; j++) {
        const int t = t0 + tx * 4 + j;
        float f0, f1, f2, f3, f4, f5, f6, f7;
        unpack2(c[j][0], f0, f1);
        unpack2(c[j][1], f2, f3);
        unpack2(c[j][2], f4, f5);
        unpack2(c[j][3], f6, f7);
        float* op = &P[((size_t)b * S_DIM + t) * (H_NUM * D_DIM) + h * D_DIM + ty * 8];
        *(float4*)op       = make_float4(f0, f1, f2, f3);
        *(float4*)(op + 4) = make_float4(f4, f5, f6, f7);
    }
}

// ---------------------------------------------------------------------------
// Kernel 3: reduce the 4 context partials into the output (deterministic).
// ---------------------------------------------------------------------------
__global__ __launch_bounds__(256) void reduce_kernel(float* __restrict__ ctx)
{
    const size_t i4 = ((size_t)blockIdx.x * 256 + threadIdx.x) * 4;
    float4 a = *(const float4*)&g_ctxp[i4];
    float4 b = *(const float4*)&g_ctxp[CTX_ELEMS + i4];
    float4 c = *(const float4*)&g_ctxp[2 * CTX_ELEMS + i4];
    float4 d = *(const float4*)&g_ctxp[3 * CTX_ELEMS + i4];
    float4 r = make_float4((a.x + b.x) + (c.x + d.x),
                           (a.y + b.y) + (c.y + d.y),
                           (a.z + b.z) + (c.z + d.z),
                           (a.w + b.w) + (c.w + d.w));
    *(float4*)&ctx[i4] = r;
}

// ---------------------------------------------------------------------------
extern "C" void kernel_launch(void* const* d_in, const int* in_sizes, int n_in,
                              void* d_out, int out_size)
{
    (void)in_sizes; (void)n_in; (void)out_size;
    const float* Q = (const float*)d_in[0];
    const float* K = (const float*)d_in[1];
    const float* V = (const float*)d_in[2];
    const int* mask = (const int*)d_in[3];

    float* ctx  = (float*)d_out;                 // (B, S, H*D)
    float* attn = ctx + CTX_ELEMS;               // (B, H, S, S)

    qk_kernel<<<dim3(8, 8, NBH), 256>>>(Q, K, mask, attn);
    pv_kernel<<<dim3(8, 4, NBH), 256>>>(V, attn);
    reduce_kernel<<<(unsigned)(CTX_ELEMS / 4 / 256), 256>>>(ctx);
}